// round 12
// baseline (speedup 1.0000x reference)
#include <cuda_runtime.h>
#include <cuda_fp16.h>
#include <cuda_bf16.h>
#include <cstdint>
#include <math.h>

// Problem sizes (fixed)
#define B_   64
#define S_   2048
#define M_   1024   // K of scores GEMM (memory feature dim)
#define D_   1024   // N of scores GEMM (decoder feature dim)

// ---------------------------------------------------------------------------
// Scratch (no allocations allowed; static device globals)
// ---------------------------------------------------------------------------
__device__ float  g_scores[B_ * S_];              // 512 KB
__device__ float  g_decf8[8][B_ * D_];            // 2 MB dec_feat partials
__device__ __half g_Wth[D_ * M_];                 // 2 MB: W_mem^T [d][k], fp16
__device__ __half g_memh[(size_t)B_ * S_ * M_];   // 256 MB: memory_bank fp16

// ---------------------------------------------------------------------------
// Helpers
// ---------------------------------------------------------------------------
__device__ __forceinline__ uint32_t smem_u32(const void* p) {
    uint32_t a;
    asm("{ .reg .u64 t; cvta.to.shared.u64 t, %1; cvt.u32.u64 %0, t; }"
        : "=r"(a) : "l"(p));
    return a;
}

__device__ __forceinline__ void cp_async16(uint32_t dst, const void* src) {
    asm volatile("cp.async.cg.shared.global [%0], [%1], 16;"
                 :: "r"(dst), "l"(src));
}
#define CP_ASYNC_COMMIT() asm volatile("cp.async.commit_group;" ::: "memory")
#define CP_ASYNC_WAIT(n)  asm volatile("cp.async.wait_group %0;" :: "n"(n) : "memory")

// ldmatrix x4 (b16): four 8x8 16-bit matrices
__device__ __forceinline__ void ldsm4(uint32_t& r0, uint32_t& r1,
                                      uint32_t& r2, uint32_t& r3, uint32_t addr) {
    asm volatile("ldmatrix.sync.aligned.m8n8.x4.shared.b16 {%0,%1,%2,%3}, [%4];"
                 : "=r"(r0), "=r"(r1), "=r"(r2), "=r"(r3) : "r"(addr));
}

// mma.sync m16n8k16 fp16 -> f32 accum
__device__ __forceinline__ void mma_f16(float* c,
                                        uint32_t a0, uint32_t a1,
                                        uint32_t a2, uint32_t a3,
                                        uint32_t b0, uint32_t b1) {
    asm volatile(
        "mma.sync.aligned.m16n8k16.row.col.f32.f16.f16.f32 "
        "{%0,%1,%2,%3}, {%4,%5,%6,%7}, {%8,%9}, {%0,%1,%2,%3};"
        : "+f"(c[0]), "+f"(c[1]), "+f"(c[2]), "+f"(c[3])
        : "r"(a0), "r"(a1), "r"(a2), "r"(a3), "r"(b0), "r"(b1));
}

// ---------------------------------------------------------------------------
// Prep kernel: one launch, four independent jobs, split by blockIdx.x
//   [0, 512)         : dec_feat partials (latency-bound -> start first)
//   [512, 1536)      : transpose W_mem -> g_Wth (fp16)
//   [1536, 2304)     : zero g_scores and ctx
//   [2304, 18688)    : convert memory_bank f32 -> fp16 (DRAM-bound bulk)
// ---------------------------------------------------------------------------
#define PREP_T0   512
#define PREP_Z0   1536
#define PREP_C0   2304
#define PREP_NB   18688
#define CONV_STRIDE (16384 * 256)      // float4 positions per sweep

__global__ __launch_bounds__(256) void prep_kernel(
    const float* __restrict__ W,               // W_mem [k][d]
    const float* __restrict__ decoder_state,
    const float* __restrict__ W_dec,
    const float* __restrict__ memory_bank,
    float* __restrict__ ctx)
{
    __shared__ float shmem[32 * 33 + 32];
    int bid = blockIdx.x;
    int tid = threadIdx.x;

    if (bid < PREP_T0) {
        // ---- dec_feat partial over one 128-wide m-chunk ----
        int idx = bid;                         // 0..511
        int dch = idx & 3;
        int bg  = ((idx >> 2) & 15) * 4;
        int mc  = idx >> 6;
        int m0  = mc * 128;
        int d   = dch * 256 + tid;

        float* ds = shmem;                     // [4][128]
        for (int i = tid; i < 4 * 128; i += 256)
            ds[i] = decoder_state[(bg + (i >> 7)) * M_ + m0 + (i & 127)];
        __syncthreads();

        float a0 = 0.f, a1 = 0.f, a2 = 0.f, a3 = 0.f;
        #pragma unroll 4
        for (int m = 0; m < 128; m++) {
            float w = W_dec[(size_t)(m0 + m) * D_ + d];
            a0 += ds[m] * w;
            a1 += ds[128 + m] * w;
            a2 += ds[256 + m] * w;
            a3 += ds[384 + m] * w;
        }
        g_decf8[mc][(bg + 0) * D_ + d] = a0;
        g_decf8[mc][(bg + 1) * D_ + d] = a1;
        g_decf8[mc][(bg + 2) * D_ + d] = a2;
        g_decf8[mc][(bg + 3) * D_ + d] = a3;
    } else if (bid < PREP_Z0) {
        // ---- transpose W_mem [k][d] -> g_Wth [d][k] (fp16) ----
        float (*t)[33] = reinterpret_cast<float (*)[33]>(shmem);
        int idx = bid - PREP_T0;
        int dblk = (idx & 31) * 32;
        int kblk = (idx >> 5) * 32;
        int tx = tid & 31;
        int ty = tid >> 5;     // 0..7
        #pragma unroll
        for (int j = 0; j < 32; j += 8)
            t[ty + j][tx] = W[(size_t)(kblk + ty + j) * D_ + dblk + tx];
        __syncthreads();
        #pragma unroll
        for (int j = 0; j < 32; j += 8)
            g_Wth[(size_t)(dblk + ty + j) * M_ + kblk + tx] =
                __float2half_rn(t[tx][ty + j]);
    } else if (bid < PREP_C0) {
        // ---- zero scores (131072) then ctx (65536) ----
        int i = (bid - PREP_Z0) * 256 + tid;
        if (i < B_ * S_) g_scores[i] = 0.0f;
        else             ctx[i - B_ * S_] = 0.0f;
    } else {
        // ---- convert memory_bank f32 -> fp16 ----
        const float4* src = reinterpret_cast<const float4*>(memory_bank);
        uint2* dst = reinterpret_cast<uint2*>(g_memh);
        size_t gid = (size_t)(bid - PREP_C0) * 256 + tid;
        #pragma unroll
        for (int j = 0; j < 8; j++) {
            size_t pos = gid + (size_t)j * CONV_STRIDE;
            float4 v = src[pos];
            __half2 h0 = __floats2half2_rn(v.x, v.y);
            __half2 h1 = __floats2half2_rn(v.z, v.w);
            uint2 o;
            o.x = *reinterpret_cast<uint32_t*>(&h0);
            o.y = *reinterpret_cast<uint32_t*>(&h1);
            dst[pos] = o;
        }
    }
}

// ---------------------------------------------------------------------------
// Scores GEMM (fp16 HMMA): C[s][d] = sum_k memh[b][s][k] * Wth[d][k], fused
//   score[s] += sum_d Wv[d] * tanh(C[s][d] + decf[b][d])
//
// mma.m16n8k16 fp16, CTA 128x64x64, 8 warps (4x2), warp tile 32x32.
// 3-stage cp.async pipeline, 3 CTAs/SM (24 warps) for latency hiding.
// smem tiles: A 128 rows, B 64 rows; 64 halfs (128 B) per row; XOR 16B-chunk
// swizzle (c ^= row&7) -> conflict-free cp.async stores and ldmatrix reads.
// ---------------------------------------------------------------------------
#define BK_      64
#define AH_BYTES (128 * BK_ * 2)                 // 16384
#define BH_BYTES (64 * BK_ * 2)                  // 8192
#define STAGE_BYTES (AH_BYTES + BH_BYTES)        // 24576
#define STAGES 3
#define SM_BYTES (STAGES * STAGE_BYTES)          // 73728

extern __shared__ float smem[];

__global__ __launch_bounds__(256, 3)
void scores_mma_kernel(const float* __restrict__ W_v)
{
    int tid  = threadIdx.x;
    int wid  = tid >> 5;
    int lane = tid & 31;
    int q    = lane & 3;          // 0..3
    int warp_m = wid & 3;         // 4 warps along s
    int warp_n = wid >> 2;        // 2 warps along d

    int d_base = blockIdx.x * 64;      // d fastest-varying -> A reuse in L2
    int s_base = blockIdx.y * 128;
    int b      = blockIdx.z;

    const __half* Abase = g_memh + ((size_t)b * S_ + s_base) * M_;
    const __half* Bbase = g_Wth + (size_t)d_base * M_;

    uint32_t smem_base = smem_u32(smem);

    // ---- cp.async coords ----
    int lrow = tid >> 3;          // base row 0..31 (i adds 32)
    int lc   = tid & 7;           // 16B chunk within 128B row
    int lcS  = lc ^ (lrow & 7);   // XOR swizzle (row&7 == lrow&7 mod 8)

    auto load_stage = [&](int kt, int st) {
        int k0 = kt * BK_;
        uint32_t dstA = smem_base + (uint32_t)st * STAGE_BYTES;
        uint32_t dstB = dstA + AH_BYTES;
        #pragma unroll
        for (int i = 0; i < 4; i++) {         // A: 128 rows
            int row = lrow + i * 32;
            cp_async16(dstA + (uint32_t)(row * 128 + lcS * 16),
                       Abase + (size_t)row * M_ + k0 + lc * 8);
        }
        #pragma unroll
        for (int i = 0; i < 2; i++) {         // B: 64 rows
            int row = lrow + i * 32;
            cp_async16(dstB + (uint32_t)(row * 128 + lcS * 16),
                       Bbase + (size_t)row * M_ + k0 + lc * 8);
        }
        CP_ASYNC_COMMIT();
    };

    // ---- ldmatrix lane-constant addressing ----
    // A (x4): m0 rows+0 k+0 | m1 rows+8 k+0 | m2 rows+0 k+8 | m3 rows+8 k+8
    int rwl = lane & 7;
    int rowA = warp_m * 32 + rwl + ((lane >> 3) & 1) * 8;
    int khA  = (lane >> 4) & 1;
    uint32_t baseA = (uint32_t)(rowA * 128);
    // B (x4): m0 n+0 k+0 | m1 n+0 k+8 | m2 n+8 k+0 | m3 n+8 k+8
    int rowB = warp_n * 32 + rwl + ((lane >> 4) & 1) * 8;
    int khB  = (lane >> 3) & 1;
    uint32_t baseB = (uint32_t)(rowB * 128);
    uint32_t offA[4], offB[4];
    #pragma unroll
    for (int ks = 0; ks < 4; ks++) {
        offA[ks] = (uint32_t)(((2 * ks + khA) ^ rwl) * 16);
        offB[ks] = (uint32_t)(((2 * ks + khB) ^ rwl) * 16);
    }

    float acc[2][4][4];
    #pragma unroll
    for (int mt = 0; mt < 2; mt++)
        #pragma unroll
        for (int nt = 0; nt < 4; nt++)
            #pragma unroll
            for (int i = 0; i < 4; i++)
                acc[mt][nt][i] = 0.0f;

    load_stage(0, 0);
    load_stage(1, 1);

    for (int kt = 0; kt < 16; kt++) {
        if (kt == 15) { CP_ASYNC_WAIT(0); } else { CP_ASYNC_WAIT(1); }
        __syncthreads();

        if (kt + 2 < 16) load_stage(kt + 2, (kt + 2) % 3);

        uint32_t stq   = smem_base + (uint32_t)(kt % 3) * STAGE_BYTES;
        uint32_t aAddr = stq + baseA;
        uint32_t bAddr = stq + AH_BYTES + baseB;

        #pragma unroll
        for (int ks = 0; ks < 4; ks++) {       // 4 x k16 = K 64
            // B fragments for all 4 nt (2 LDSM.x4; r0,r1 = nt even; r2,r3 = odd)
            uint32_t bfr[8];
            #pragma unroll
            for (int ntp = 0; ntp < 2; ntp++)
                ldsm4(bfr[ntp * 4 + 0], bfr[ntp * 4 + 1],
                      bfr[ntp * 4 + 2], bfr[ntp * 4 + 3],
                      bAddr + (uint32_t)(ntp * 16 * 128) + offB[ks]);

            #pragma unroll
            for (int mt = 0; mt < 2; mt++) {
                uint32_t a0, a1, a2, a3;
                ldsm4(a0, a1, a2, a3,
                      aAddr + (uint32_t)(mt * 16 * 128) + offA[ks]);
                #pragma unroll
                for (int nt = 0; nt < 4; nt++) {
                    int bi = (nt >> 1) * 4 + (nt & 1) * 2;
                    mma_f16(acc[mt][nt], a0, a1, a2, a3, bfr[bi], bfr[bi + 1]);
                }
            }
        }
    }

    // ---- epilogue: score[s] += sum_d Wv[d]*tanh(C + decf[d]) ----
    __syncthreads();
    float* s_df = smem;           // [64]
    float* s_wv = smem + 64;      // [64]
    if (tid < 64) {
        int gi = b * D_ + d_base + tid;
        float df = g_decf8[0][gi];
        #pragma unroll
        for (int c = 1; c < 8; c++) df += g_decf8[c][gi];
        s_df[tid] = df;
    } else if (tid < 128) {
        s_wv[tid - 64] = W_v[d_base + tid - 64];
    }
    __syncthreads();

    float part[4] = {0.f, 0.f, 0.f, 0.f};
    #pragma unroll
    for (int mt = 0; mt < 2; mt++) {
        #pragma unroll
        for (int nt = 0; nt < 4; nt++) {
            int col0 = warp_n * 32 + nt * 8 + 2 * q;
            float wv0 = s_wv[col0], wv1 = s_wv[col0 + 1];
            float df0 = s_df[col0], df1 = s_df[col0 + 1];
            part[2 * mt]     += wv0 * tanhf(acc[mt][nt][0] + df0)
                              + wv1 * tanhf(acc[mt][nt][1] + df1);
            part[2 * mt + 1] += wv0 * tanhf(acc[mt][nt][2] + df0)
                              + wv1 * tanhf(acc[mt][nt][3] + df1);
        }
    }
    #pragma unroll
    for (int i = 0; i < 4; i++) {
        part[i] += __shfl_xor_sync(0xFFFFFFFFu, part[i], 1);
        part[i] += __shfl_xor_sync(0xFFFFFFFFu, part[i], 2);
    }
    if (q == 0) {
        int grp = lane >> 2;
        int rbase = b * S_ + s_base + warp_m * 32 + grp;
        atomicAdd(&g_scores[rbase],      part[0]);
        atomicAdd(&g_scores[rbase + 8],  part[1]);
        atomicAdd(&g_scores[rbase + 16], part[2]);
        atomicAdd(&g_scores[rbase + 24], part[3]);
    }
}

// ---------------------------------------------------------------------------
// Fused masked softmax + context (context reads fp16 memory copy: half DRAM).
// grid (8 s-chunks of 256, 64 b), block 256.
// ---------------------------------------------------------------------------
#define CCHUNK 256

__global__ __launch_bounds__(256) void softmax_context_kernel(
    const int* __restrict__ src_mask,
    float* __restrict__ attn_out,
    float* __restrict__ ctx_out)
{
    __shared__ float red[8];
    __shared__ float sa[CCHUNK];
    int tid = threadIdx.x;
    int lane = tid & 31, wid = tid >> 5;
    int b  = blockIdx.y;
    int s0 = blockIdx.x * CCHUNK;

    // ---- softmax stats over the whole row (identical in all 8 CTAs of b) ----
    float v[8];
    float mx = -3.4e38f;
    #pragma unroll
    for (int j = 0; j < 8; j++) {
        int idx = tid + j * 256;
        float s = g_scores[b * S_ + idx];
        if (src_mask[b * S_ + idx] == 0) s = -3.4e38f;
        v[j] = s;
        mx = fmaxf(mx, s);
    }
    #pragma unroll
    for (int off = 16; off > 0; off >>= 1)
        mx = fmaxf(mx, __shfl_xor_sync(0xFFFFFFFFu, mx, off));
    if (lane == 0) red[wid] = mx;
    __syncthreads();
    if (tid == 0) {
        float m2 = red[0];
        #pragma unroll
        for (int w = 1; w < 8; w++) m2 = fmaxf(m2, red[w]);
        red[0] = m2;
    }
    __syncthreads();
    mx = red[0];
    __syncthreads();

    float sum = 0.0f;
    #pragma unroll
    for (int j = 0; j < 8; j++)
        sum += __expf(v[j] - mx);
    #pragma unroll
    for (int off = 16; off > 0; off >>= 1)
        sum += __shfl_xor_sync(0xFFFFFFFFu, sum, off);
    if (lane == 0) red[wid] = sum;
    __syncthreads();
    if (tid == 0) {
        float s2 = 0.0f;
        #pragma unroll
        for (int w = 0; w < 8; w++) s2 += red[w];
        red[0] = s2;
    }
    __syncthreads();
    float inv = 1.0f / red[0];

    // ---- attn for this CTA's chunk ----
    float a = __expf(v[blockIdx.x] - mx) * inv;
    attn_out[b * S_ + s0 + tid] = a;
    sa[tid] = a;
    __syncthreads();

    // ---- context partial from fp16 memory: 8 m per thread, 2-way s split ----
    int mgrp = (tid & 127) * 8;               // 8 consecutive m
    int sp   = tid >> 7;                      // s parity 0/1
    const uint4* base = reinterpret_cast<const uint4*>(
        g_memh + ((size_t)b * S_ + s0) * M_ + mgrp);
    float acc[8];
    #pragma unroll
    for (int i = 0; i < 8; i++) acc[i] = 0.0f;

    for (int s = sp; s < CCHUNK; s += 2) {
        float w = sa[s];
        uint4 pk = base[(size_t)s * (M_ / 8)];
        __half2 h0 = *reinterpret_cast<__half2*>(&pk.x);
        __half2 h1 = *reinterpret_cast<__half2*>(&pk.y);
        __half2 h2 = *reinterpret_cast<__half2*>(&pk.z);
        __half2 h3 = *reinterpret_cast<__half2*>(&pk.w);
        float2 f0 = __half22float2(h0);
        float2 f1 = __half22float2(h1);
        float2 f2 = __half22float2(h2);
        float2 f3 = __half22float2(h3);
        acc[0] += w * f0.x; acc[1] += w * f0.y;
        acc[2] += w * f1.x; acc[3] += w * f1.y;
        acc[4] += w * f2.x; acc[5] += w * f2.y;
        acc[6] += w * f3.x; acc[7] += w * f3.y;
    }
    float* dst = ctx_out + b * M_ + mgrp;
    #pragma unroll
    for (int i = 0; i < 8; i++)
        atomicAdd(dst + i, acc[i]);
}

// ---------------------------------------------------------------------------
// Launch
// ---------------------------------------------------------------------------
extern "C" void kernel_launch(void* const* d_in, const int* in_sizes, int n_in,
                              void* d_out, int out_size)
{
    const float* decoder_state = (const float*)d_in[0];
    const float* memory_bank   = (const float*)d_in[1];
    const int*   src_mask      = (const int*)  d_in[2];
    const float* W_v           = (const float*)d_in[3];
    const float* W_dec         = (const float*)d_in[4];
    const float* W_mem         = (const float*)d_in[5];

    float* out  = (float*)d_out;
    float* ctx  = out;                 // [64, 1024]
    float* attn = out + B_ * M_;       // [64, 2048]

    cudaFuncSetAttribute(scores_mma_kernel,
                         cudaFuncAttributeMaxDynamicSharedMemorySize, SM_BYTES);

    prep_kernel<<<PREP_NB, 256>>>(W_mem, decoder_state, W_dec, memory_bank, ctx);
    scores_mma_kernel<<<dim3(D_ / 64, S_ / 128, B_), 256, SM_BYTES>>>(W_v);
    softmax_context_kernel<<<dim3(S_ / CCHUNK, B_), 256>>>(src_mask, attn, ctx);
}

// round 13
// speedup vs baseline: 1.0971x; 1.0971x over previous
#include <cuda_runtime.h>
#include <cuda_fp16.h>
#include <cuda_bf16.h>
#include <cstdint>
#include <math.h>

// Problem sizes (fixed)
#define B_   64
#define S_   2048
#define M_   1024   // K of scores GEMM (memory feature dim)
#define D_   1024   // N of scores GEMM (decoder feature dim)

// ---------------------------------------------------------------------------
// Scratch (no allocations allowed; static device globals)
// ---------------------------------------------------------------------------
__device__ float  g_scores[B_ * S_];              // 512 KB
__device__ float  g_decf8[8][B_ * D_];            // 2 MB dec_feat partials
__device__ __half g_Wth[D_ * M_];                 // 2 MB: W_mem^T [d][k], fp16
__device__ __half g_memh[(size_t)B_ * S_ * M_];   // 256 MB: memory_bank fp16

// ---------------------------------------------------------------------------
// Helpers
// ---------------------------------------------------------------------------
__device__ __forceinline__ uint32_t smem_u32(const void* p) {
    uint32_t a;
    asm("{ .reg .u64 t; cvta.to.shared.u64 t, %1; cvt.u32.u64 %0, t; }"
        : "=r"(a) : "l"(p));
    return a;
}

__device__ __forceinline__ void cp_async16(uint32_t dst, const void* src) {
    asm volatile("cp.async.cg.shared.global [%0], [%1], 16;"
                 :: "r"(dst), "l"(src));
}
#define CP_ASYNC_COMMIT() asm volatile("cp.async.commit_group;" ::: "memory")
#define CP_ASYNC_WAIT(n)  asm volatile("cp.async.wait_group %0;" :: "n"(n) : "memory")

// ldmatrix x4 (b16): four 8x8 16-bit matrices
__device__ __forceinline__ void ldsm4(uint32_t& r0, uint32_t& r1,
                                      uint32_t& r2, uint32_t& r3, uint32_t addr) {
    asm volatile("ldmatrix.sync.aligned.m8n8.x4.shared.b16 {%0,%1,%2,%3}, [%4];"
                 : "=r"(r0), "=r"(r1), "=r"(r2), "=r"(r3) : "r"(addr));
}

// mma.sync m16n8k16 fp16 -> f32 accum
__device__ __forceinline__ void mma_f16(float* c,
                                        uint32_t a0, uint32_t a1,
                                        uint32_t a2, uint32_t a3,
                                        uint32_t b0, uint32_t b1) {
    asm volatile(
        "mma.sync.aligned.m16n8k16.row.col.f32.f16.f16.f32 "
        "{%0,%1,%2,%3}, {%4,%5,%6,%7}, {%8,%9}, {%0,%1,%2,%3};"
        : "+f"(c[0]), "+f"(c[1]), "+f"(c[2]), "+f"(c[3])
        : "r"(a0), "r"(a1), "r"(a2), "r"(a3), "r"(b0), "r"(b1));
}

// hardware tanh (MUFU.TANH, sm_75+). rel err ~2^-11 — same scale as fp16
// input rounding; fits precision budget.
__device__ __forceinline__ float tanh_fast(float x) {
    float y;
    asm("tanh.approx.f32 %0, %1;" : "=f"(y) : "f"(x));
    return y;
}

// ---------------------------------------------------------------------------
// Prep kernel: one launch, four independent jobs, split by blockIdx.x
//   [0, 512)         : dec_feat partials (latency-bound -> start first)
//   [512, 1536)      : transpose W_mem -> g_Wth (fp16)
//   [1536, 2304)     : zero g_scores and ctx
//   [2304, 18688)    : convert memory_bank f32 -> fp16 (DRAM-bound bulk)
// ---------------------------------------------------------------------------
#define PREP_T0   512
#define PREP_Z0   1536
#define PREP_C0   2304
#define PREP_NB   18688
#define CONV_STRIDE (16384 * 256)      // float4 positions per sweep

__global__ __launch_bounds__(256) void prep_kernel(
    const float* __restrict__ W,               // W_mem [k][d]
    const float* __restrict__ decoder_state,
    const float* __restrict__ W_dec,
    const float* __restrict__ memory_bank,
    float* __restrict__ ctx)
{
    __shared__ float shmem[32 * 33 + 32];
    int bid = blockIdx.x;
    int tid = threadIdx.x;

    if (bid < PREP_T0) {
        // ---- dec_feat partial over one 128-wide m-chunk ----
        int idx = bid;                         // 0..511
        int dch = idx & 3;
        int bg  = ((idx >> 2) & 15) * 4;
        int mc  = idx >> 6;
        int m0  = mc * 128;
        int d   = dch * 256 + tid;

        float* ds = shmem;                     // [4][128]
        for (int i = tid; i < 4 * 128; i += 256)
            ds[i] = decoder_state[(bg + (i >> 7)) * M_ + m0 + (i & 127)];
        __syncthreads();

        float a0 = 0.f, a1 = 0.f, a2 = 0.f, a3 = 0.f;
        #pragma unroll 4
        for (int m = 0; m < 128; m++) {
            float w = W_dec[(size_t)(m0 + m) * D_ + d];
            a0 += ds[m] * w;
            a1 += ds[128 + m] * w;
            a2 += ds[256 + m] * w;
            a3 += ds[384 + m] * w;
        }
        g_decf8[mc][(bg + 0) * D_ + d] = a0;
        g_decf8[mc][(bg + 1) * D_ + d] = a1;
        g_decf8[mc][(bg + 2) * D_ + d] = a2;
        g_decf8[mc][(bg + 3) * D_ + d] = a3;
    } else if (bid < PREP_Z0) {
        // ---- transpose W_mem [k][d] -> g_Wth [d][k] (fp16) ----
        float (*t)[33] = reinterpret_cast<float (*)[33]>(shmem);
        int idx = bid - PREP_T0;
        int dblk = (idx & 31) * 32;
        int kblk = (idx >> 5) * 32;
        int tx = tid & 31;
        int ty = tid >> 5;     // 0..7
        #pragma unroll
        for (int j = 0; j < 32; j += 8)
            t[ty + j][tx] = W[(size_t)(kblk + ty + j) * D_ + dblk + tx];
        __syncthreads();
        #pragma unroll
        for (int j = 0; j < 32; j += 8)
            g_Wth[(size_t)(dblk + ty + j) * M_ + kblk + tx] =
                __float2half_rn(t[tx][ty + j]);
    } else if (bid < PREP_C0) {
        // ---- zero scores (131072) then ctx (65536) ----
        int i = (bid - PREP_Z0) * 256 + tid;
        if (i < B_ * S_) g_scores[i] = 0.0f;
        else             ctx[i - B_ * S_] = 0.0f;
    } else {
        // ---- convert memory_bank f32 -> fp16 ----
        const float4* src = reinterpret_cast<const float4*>(memory_bank);
        uint2* dst = reinterpret_cast<uint2*>(g_memh);
        size_t gid = (size_t)(bid - PREP_C0) * 256 + tid;
        #pragma unroll
        for (int j = 0; j < 8; j++) {
            size_t pos = gid + (size_t)j * CONV_STRIDE;
            float4 v = src[pos];
            __half2 h0 = __floats2half2_rn(v.x, v.y);
            __half2 h1 = __floats2half2_rn(v.z, v.w);
            uint2 o;
            o.x = *reinterpret_cast<uint32_t*>(&h0);
            o.y = *reinterpret_cast<uint32_t*>(&h1);
            dst[pos] = o;
        }
    }
}

// ---------------------------------------------------------------------------
// Scores GEMM (fp16 HMMA): C[s][d] = sum_k memh[b][s][k] * Wth[d][k], fused
//   score[s] += sum_d Wv[d] * tanh(C[s][d] + decf[b][d])
//
// mma.m16n8k16 fp16, CTA 128x128x64, 8 warps (4x2), warp tile 32x64.
// 3-stage cp.async pipeline; BK=64 -> 16 iterations. (R11 config — best)
// ---------------------------------------------------------------------------
#define BK_      64
#define AH_BYTES (128 * BK_ * 2)                 // 16384
#define STAGE_BYTES (2 * AH_BYTES)               // 32768
#define STAGES 3
#define SM_BYTES (STAGES * STAGE_BYTES)          // 98304

extern __shared__ float smem[];

__global__ __launch_bounds__(256, 2)
void scores_mma_kernel(const float* __restrict__ W_v)
{
    int tid  = threadIdx.x;
    int wid  = tid >> 5;
    int lane = tid & 31;
    int q    = lane & 3;          // 0..3
    int warp_m = wid & 3;         // 4 warps along s
    int warp_n = wid >> 2;        // 2 warps along d

    int d_base = blockIdx.x * 128;     // d fastest-varying -> A reuse in L2
    int s_base = blockIdx.y * 128;
    int b      = blockIdx.z;

    const __half* Abase = g_memh + ((size_t)b * S_ + s_base) * M_;
    const __half* Bbase = g_Wth + (size_t)d_base * M_;

    uint32_t smem_base = smem_u32(smem);

    // ---- cp.async coords: 1024 16B-chunks per tile, 4 per thread ----
    int lrow = tid >> 3;          // base row 0..31 (i adds 32)
    int lc   = tid & 7;           // 16B chunk within 128B row
    int lcS  = lc ^ (lrow & 7);   // XOR swizzle (row&7 == lrow&7 mod 8)

    auto load_stage = [&](int kt, int st) {
        int k0 = kt * BK_;
        uint32_t dstA = smem_base + (uint32_t)st * STAGE_BYTES;
        uint32_t dstB = dstA + AH_BYTES;
        #pragma unroll
        for (int i = 0; i < 4; i++) {
            int row = lrow + i * 32;
            cp_async16(dstA + (uint32_t)(row * 128 + lcS * 16),
                       Abase + (size_t)row * M_ + k0 + lc * 8);
        }
        #pragma unroll
        for (int i = 0; i < 4; i++) {
            int row = lrow + i * 32;
            cp_async16(dstB + (uint32_t)(row * 128 + lcS * 16),
                       Bbase + (size_t)row * M_ + k0 + lc * 8);
        }
        CP_ASYNC_COMMIT();
    };

    // ---- ldmatrix lane-constant addressing ----
    // A (x4): m0 rows+0 k+0 | m1 rows+8 k+0 | m2 rows+0 k+8 | m3 rows+8 k+8
    int rwl = lane & 7;
    int rowA = warp_m * 32 + rwl + ((lane >> 3) & 1) * 8;
    int khA  = (lane >> 4) & 1;
    uint32_t baseA = (uint32_t)(rowA * 128);
    // B (x4): m0 n+0 k+0 | m1 n+0 k+8 | m2 n+8 k+0 | m3 n+8 k+8
    int rowB = warp_n * 64 + rwl + ((lane >> 4) & 1) * 8;
    int khB  = (lane >> 3) & 1;
    uint32_t baseB = (uint32_t)(rowB * 128);
    uint32_t offA[4], offB[4];
    #pragma unroll
    for (int ks = 0; ks < 4; ks++) {
        offA[ks] = (uint32_t)(((2 * ks + khA) ^ rwl) * 16);
        offB[ks] = (uint32_t)(((2 * ks + khB) ^ rwl) * 16);
    }

    float acc[2][8][4];
    #pragma unroll
    for (int mt = 0; mt < 2; mt++)
        #pragma unroll
        for (int nt = 0; nt < 8; nt++)
            #pragma unroll
            for (int i = 0; i < 4; i++)
                acc[mt][nt][i] = 0.0f;

    load_stage(0, 0);
    load_stage(1, 1);

    for (int kt = 0; kt < 16; kt++) {
        if (kt == 15) { CP_ASYNC_WAIT(0); } else { CP_ASYNC_WAIT(1); }
        __syncthreads();

        if (kt + 2 < 16) load_stage(kt + 2, (kt + 2) % 3);

        uint32_t stq   = smem_base + (uint32_t)(kt % 3) * STAGE_BYTES;
        uint32_t aAddr = stq + baseA;
        uint32_t bAddr = stq + AH_BYTES + baseB;

        #pragma unroll
        for (int ks = 0; ks < 4; ks++) {       // 4 x k16 = K 64
            // B fragments for all 8 nt (4 LDSM.x4; r0,r1 = nt even; r2,r3 = odd)
            uint32_t bfr[16];
            #pragma unroll
            for (int ntp = 0; ntp < 4; ntp++)
                ldsm4(bfr[ntp * 4 + 0], bfr[ntp * 4 + 1],
                      bfr[ntp * 4 + 2], bfr[ntp * 4 + 3],
                      bAddr + (uint32_t)(ntp * 16 * 128) + offB[ks]);

            #pragma unroll
            for (int mt = 0; mt < 2; mt++) {
                uint32_t a0, a1, a2, a3;
                ldsm4(a0, a1, a2, a3,
                      aAddr + (uint32_t)(mt * 16 * 128) + offA[ks]);
                #pragma unroll
                for (int nt = 0; nt < 8; nt++) {
                    int bi = (nt >> 1) * 4 + (nt & 1) * 2;
                    mma_f16(acc[mt][nt], a0, a1, a2, a3, bfr[bi], bfr[bi + 1]);
                }
            }
        }
    }

    // ---- epilogue: score[s] += sum_d Wv[d]*tanh(C + decf[d]) ----
    __syncthreads();
    float* s_df = smem;           // [128]
    float* s_wv = smem + 128;     // [128]
    if (tid < 128) {
        int gi = b * D_ + d_base + tid;
        float df = g_decf8[0][gi];
        #pragma unroll
        for (int c = 1; c < 8; c++) df += g_decf8[c][gi];
        s_df[tid] = df;
    } else {
        s_wv[tid - 128] = W_v[d_base + tid - 128];
    }
    __syncthreads();

    float part[4] = {0.f, 0.f, 0.f, 0.f};
    #pragma unroll
    for (int mt = 0; mt < 2; mt++) {
        #pragma unroll
        for (int nt = 0; nt < 8; nt++) {
            int col0 = warp_n * 64 + nt * 8 + 2 * q;
            float wv0 = s_wv[col0], wv1 = s_wv[col0 + 1];
            float df0 = s_df[col0], df1 = s_df[col0 + 1];
            part[2 * mt]     += wv0 * tanh_fast(acc[mt][nt][0] + df0)
                              + wv1 * tanh_fast(acc[mt][nt][1] + df1);
            part[2 * mt + 1] += wv0 * tanh_fast(acc[mt][nt][2] + df0)
                              + wv1 * tanh_fast(acc[mt][nt][3] + df1);
        }
    }
    #pragma unroll
    for (int i = 0; i < 4; i++) {
        part[i] += __shfl_xor_sync(0xFFFFFFFFu, part[i], 1);
        part[i] += __shfl_xor_sync(0xFFFFFFFFu, part[i], 2);
    }
    if (q == 0) {
        int grp = lane >> 2;
        int rbase = b * S_ + s_base + warp_m * 32 + grp;
        atomicAdd(&g_scores[rbase],      part[0]);
        atomicAdd(&g_scores[rbase + 8],  part[1]);
        atomicAdd(&g_scores[rbase + 16], part[2]);
        atomicAdd(&g_scores[rbase + 24], part[3]);
    }
}

// ---------------------------------------------------------------------------
// Fused masked softmax + context (context reads fp16 memory copy: half DRAM).
// grid (8 s-chunks of 256, 64 b), block 256.
// ---------------------------------------------------------------------------
#define CCHUNK 256

__global__ __launch_bounds__(256) void softmax_context_kernel(
    const int* __restrict__ src_mask,
    float* __restrict__ attn_out,
    float* __restrict__ ctx_out)
{
    __shared__ float red[8];
    __shared__ float sa[CCHUNK];
    int tid = threadIdx.x;
    int lane = tid & 31, wid = tid >> 5;
    int b  = blockIdx.y;
    int s0 = blockIdx.x * CCHUNK;

    // ---- softmax stats over the whole row (identical in all 8 CTAs of b) ----
    float v[8];
    float mx = -3.4e38f;
    #pragma unroll
    for (int j = 0; j < 8; j++) {
        int idx = tid + j * 256;
        float s = g_scores[b * S_ + idx];
        if (src_mask[b * S_ + idx] == 0) s = -3.4e38f;
        v[j] = s;
        mx = fmaxf(mx, s);
    }
    #pragma unroll
    for (int off = 16; off > 0; off >>= 1)
        mx = fmaxf(mx, __shfl_xor_sync(0xFFFFFFFFu, mx, off));
    if (lane == 0) red[wid] = mx;
    __syncthreads();
    if (tid == 0) {
        float m2 = red[0];
        #pragma unroll
        for (int w = 1; w < 8; w++) m2 = fmaxf(m2, red[w]);
        red[0] = m2;
    }
    __syncthreads();
    mx = red[0];
    __syncthreads();

    float sum = 0.0f;
    #pragma unroll
    for (int j = 0; j < 8; j++)
        sum += __expf(v[j] - mx);
    #pragma unroll
    for (int off = 16; off > 0; off >>= 1)
        sum += __shfl_xor_sync(0xFFFFFFFFu, sum, off);
    if (lane == 0) red[wid] = sum;
    __syncthreads();
    if (tid == 0) {
        float s2 = 0.0f;
        #pragma unroll
        for (int w = 0; w < 8; w++) s2 += red[w];
        red[0] = s2;
    }
    __syncthreads();
    float inv = 1.0f / red[0];

    // ---- attn for this CTA's chunk ----
    float a = __expf(v[blockIdx.x] - mx) * inv;
    attn_out[b * S_ + s0 + tid] = a;
    sa[tid] = a;
    __syncthreads();

    // ---- context partial from fp16 memory: 8 m per thread, 2-way s split ----
    int mgrp = (tid & 127) * 8;               // 8 consecutive m
    int sp   = tid >> 7;                      // s parity 0/1
    const uint4* base = reinterpret_cast<const uint4*>(
        g_memh + ((size_t)b * S_ + s0) * M_ + mgrp);
    float acc[8];
    #pragma unroll
    for (int i = 0; i < 8; i++) acc[i] = 0.0f;

    for (int s = sp; s < CCHUNK; s += 2) {
        float w = sa[s];
        uint4 pk = base[(size_t)s * (M_ / 8)];
        __half2 h0 = *reinterpret_cast<__half2*>(&pk.x);
        __half2 h1 = *reinterpret_cast<__half2*>(&pk.y);
        __half2 h2 = *reinterpret_cast<__half2*>(&pk.z);
        __half2 h3 = *reinterpret_cast<__half2*>(&pk.w);
        float2 f0 = __half22float2(h0);
        float2 f1 = __half22float2(h1);
        float2 f2 = __half22float2(h2);
        float2 f3 = __half22float2(h3);
        acc[0] += w * f0.x; acc[1] += w * f0.y;
        acc[2] += w * f1.x; acc[3] += w * f1.y;
        acc[4] += w * f2.x; acc[5] += w * f2.y;
        acc[6] += w * f3.x; acc[7] += w * f3.y;
    }
    float* dst = ctx_out + b * M_ + mgrp;
    #pragma unroll
    for (int i = 0; i < 8; i++)
        atomicAdd(dst + i, acc[i]);
}

// ---------------------------------------------------------------------------
// Launch
// ---------------------------------------------------------------------------
extern "C" void kernel_launch(void* const* d_in, const int* in_sizes, int n_in,
                              void* d_out, int out_size)
{
    const float* decoder_state = (const float*)d_in[0];
    const float* memory_bank   = (const float*)d_in[1];
    const int*   src_mask      = (const int*)  d_in[2];
    const float* W_v           = (const float*)d_in[3];
    const float* W_dec         = (const float*)d_in[4];
    const float* W_mem         = (const float*)d_in[5];

    float* out  = (float*)d_out;
    float* ctx  = out;                 // [64, 1024]
    float* attn = out + B_ * M_;       // [64, 2048]

    cudaFuncSetAttribute(scores_mma_kernel,
                         cudaFuncAttributeMaxDynamicSharedMemorySize, SM_BYTES);

    prep_kernel<<<PREP_NB, 256>>>(W_mem, decoder_state, W_dec, memory_bank, ctx);
    scores_mma_kernel<<<dim3(D_ / 128, S_ / 128, B_), 256, SM_BYTES>>>(W_v);
    softmax_context_kernel<<<dim3(S_ / CCHUNK, B_), 256>>>(src_mask, attn, ctx);
}

// round 14
// speedup vs baseline: 1.1311x; 1.0310x over previous
#include <cuda_runtime.h>
#include <cuda_fp16.h>
#include <cuda_bf16.h>
#include <cstdint>
#include <math.h>

// Problem sizes (fixed)
#define B_   64
#define S_   2048
#define M_   1024   // K of scores GEMM (memory feature dim)
#define D_   1024   // N of scores GEMM (decoder feature dim)

// ---------------------------------------------------------------------------
// Scratch (no allocations allowed; static device globals)
// ---------------------------------------------------------------------------
__device__ float  g_spart[8][B_ * S_];            // 4 MB: score partials per d-tile
__device__ float  g_decf8[8][B_ * D_];            // 2 MB dec_feat partials
__device__ __half g_Wth[D_ * M_];                 // 2 MB: W_mem^T [d][k], fp16
__device__ __half g_memh[(size_t)B_ * S_ * M_];   // 256 MB: memory_bank fp16

// ---------------------------------------------------------------------------
// Helpers
// ---------------------------------------------------------------------------
__device__ __forceinline__ uint32_t smem_u32(const void* p) {
    uint32_t a;
    asm("{ .reg .u64 t; cvta.to.shared.u64 t, %1; cvt.u32.u64 %0, t; }"
        : "=r"(a) : "l"(p));
    return a;
}

__device__ __forceinline__ void cp_async16(uint32_t dst, const void* src) {
    asm volatile("cp.async.cg.shared.global [%0], [%1], 16;"
                 :: "r"(dst), "l"(src));
}
#define CP_ASYNC_COMMIT() asm volatile("cp.async.commit_group;" ::: "memory")
#define CP_ASYNC_WAIT(n)  asm volatile("cp.async.wait_group %0;" :: "n"(n) : "memory")

// ldmatrix x4 (b16): four 8x8 16-bit matrices
__device__ __forceinline__ void ldsm4(uint32_t& r0, uint32_t& r1,
                                      uint32_t& r2, uint32_t& r3, uint32_t addr) {
    asm volatile("ldmatrix.sync.aligned.m8n8.x4.shared.b16 {%0,%1,%2,%3}, [%4];"
                 : "=r"(r0), "=r"(r1), "=r"(r2), "=r"(r3) : "r"(addr));
}

// mma.sync m16n8k16 fp16 -> f32 accum
__device__ __forceinline__ void mma_f16(float* c,
                                        uint32_t a0, uint32_t a1,
                                        uint32_t a2, uint32_t a3,
                                        uint32_t b0, uint32_t b1) {
    asm volatile(
        "mma.sync.aligned.m16n8k16.row.col.f32.f16.f16.f32 "
        "{%0,%1,%2,%3}, {%4,%5,%6,%7}, {%8,%9}, {%0,%1,%2,%3};"
        : "+f"(c[0]), "+f"(c[1]), "+f"(c[2]), "+f"(c[3])
        : "r"(a0), "r"(a1), "r"(a2), "r"(a3), "r"(b0), "r"(b1));
}

// hardware tanh (MUFU.TANH, sm_75+)
__device__ __forceinline__ float tanh_fast(float x) {
    float y;
    asm("tanh.approx.f32 %0, %1;" : "=f"(y) : "f"(x));
    return y;
}

// ---------------------------------------------------------------------------
// Prep kernel: one launch, four independent jobs, split by blockIdx.x
//   [0, 512)         : dec_feat partials (latency-bound -> start first)
//   [512, 1536)      : transpose W_mem -> g_Wth (fp16)
//   [1536, 1792)     : zero ctx
//   [1792, 18176)    : convert memory_bank f32 -> fp16 (DRAM-bound bulk)
// ---------------------------------------------------------------------------
#define PREP_T0   512
#define PREP_Z0   1536
#define PREP_C0   1792
#define PREP_NB   18176
#define CONV_STRIDE (16384 * 256)      // float4 positions per sweep

__global__ __launch_bounds__(256) void prep_kernel(
    const float* __restrict__ W,               // W_mem [k][d]
    const float* __restrict__ decoder_state,
    const float* __restrict__ W_dec,
    const float* __restrict__ memory_bank,
    float* __restrict__ ctx)
{
    __shared__ float shmem[32 * 33 + 32];
    int bid = blockIdx.x;
    int tid = threadIdx.x;

    if (bid < PREP_T0) {
        // ---- dec_feat partial over one 128-wide m-chunk ----
        int idx = bid;                         // 0..511
        int dch = idx & 3;
        int bg  = ((idx >> 2) & 15) * 4;
        int mc  = idx >> 6;
        int m0  = mc * 128;
        int d   = dch * 256 + tid;

        float* ds = shmem;                     // [4][128]
        for (int i = tid; i < 4 * 128; i += 256)
            ds[i] = decoder_state[(bg + (i >> 7)) * M_ + m0 + (i & 127)];
        __syncthreads();

        float a0 = 0.f, a1 = 0.f, a2 = 0.f, a3 = 0.f;
        #pragma unroll 4
        for (int m = 0; m < 128; m++) {
            float w = W_dec[(size_t)(m0 + m) * D_ + d];
            a0 += ds[m] * w;
            a1 += ds[128 + m] * w;
            a2 += ds[256 + m] * w;
            a3 += ds[384 + m] * w;
        }
        g_decf8[mc][(bg + 0) * D_ + d] = a0;
        g_decf8[mc][(bg + 1) * D_ + d] = a1;
        g_decf8[mc][(bg + 2) * D_ + d] = a2;
        g_decf8[mc][(bg + 3) * D_ + d] = a3;
    } else if (bid < PREP_Z0) {
        // ---- transpose W_mem [k][d] -> g_Wth [d][k] (fp16) ----
        float (*t)[33] = reinterpret_cast<float (*)[33]>(shmem);
        int idx = bid - PREP_T0;
        int dblk = (idx & 31) * 32;
        int kblk = (idx >> 5) * 32;
        int tx = tid & 31;
        int ty = tid >> 5;     // 0..7
        #pragma unroll
        for (int j = 0; j < 32; j += 8)
            t[ty + j][tx] = W[(size_t)(kblk + ty + j) * D_ + dblk + tx];
        __syncthreads();
        #pragma unroll
        for (int j = 0; j < 32; j += 8)
            g_Wth[(size_t)(dblk + ty + j) * M_ + kblk + tx] =
                __float2half_rn(t[tx][ty + j]);
    } else if (bid < PREP_C0) {
        // ---- zero ctx (65536 elems, 256 blocks x 256) ----
        int i = (bid - PREP_Z0) * 256 + tid;
        ctx[i] = 0.0f;
    } else {
        // ---- convert memory_bank f32 -> fp16 ----
        const float4* src = reinterpret_cast<const float4*>(memory_bank);
        uint2* dst = reinterpret_cast<uint2*>(g_memh);
        size_t gid = (size_t)(bid - PREP_C0) * 256 + tid;
        #pragma unroll
        for (int j = 0; j < 8; j++) {
            size_t pos = gid + (size_t)j * CONV_STRIDE;
            float4 v = src[pos];
            __half2 h0 = __floats2half2_rn(v.x, v.y);
            __half2 h1 = __floats2half2_rn(v.z, v.w);
            uint2 o;
            o.x = *reinterpret_cast<uint32_t*>(&h0);
            o.y = *reinterpret_cast<uint32_t*>(&h1);
            dst[pos] = o;
        }
    }
}

// ---------------------------------------------------------------------------
// Scores GEMM (fp16 HMMA): C[s][d] = sum_k memh[b][s][k] * Wth[d][k], fused
//   spart[dblk][s] = sum_{d in tile} Wv[d] * tanh(C[s][d] + decf[b][d])
//
// mma.m16n8k16 fp16, CTA 128x128x64, 8 warps (4x2), warp tile 32x64.
// 3-stage cp.async pipeline; B fragments double-buffered across ks to
// remove the LDSM->MMA dependency bubble at each k16 step.
// ---------------------------------------------------------------------------
#define BK_      64
#define AH_BYTES (128 * BK_ * 2)                 // 16384
#define STAGE_BYTES (2 * AH_BYTES)               // 32768
#define STAGES 3
#define SM_BYTES (STAGES * STAGE_BYTES)          // 98304

extern __shared__ float smem[];

__global__ __launch_bounds__(256, 2)
void scores_mma_kernel(const float* __restrict__ W_v)
{
    int tid  = threadIdx.x;
    int wid  = tid >> 5;
    int lane = tid & 31;
    int q    = lane & 3;          // 0..3
    int warp_m = wid & 3;         // 4 warps along s
    int warp_n = wid >> 2;        // 2 warps along d

    int d_base = blockIdx.x * 128;     // d fastest-varying -> A reuse in L2
    int s_base = blockIdx.y * 128;
    int b      = blockIdx.z;

    const __half* Abase = g_memh + ((size_t)b * S_ + s_base) * M_;
    const __half* Bbase = g_Wth + (size_t)d_base * M_;

    uint32_t smem_base = smem_u32(smem);

    // ---- cp.async coords: 1024 16B-chunks per tile, 4 per thread ----
    int lrow = tid >> 3;          // base row 0..31 (i adds 32)
    int lc   = tid & 7;           // 16B chunk within 128B row
    int lcS  = lc ^ (lrow & 7);   // XOR swizzle (row&7 == lrow&7 mod 8)

    auto load_stage = [&](int kt, int st) {
        int k0 = kt * BK_;
        uint32_t dstA = smem_base + (uint32_t)st * STAGE_BYTES;
        uint32_t dstB = dstA + AH_BYTES;
        #pragma unroll
        for (int i = 0; i < 4; i++) {
            int row = lrow + i * 32;
            cp_async16(dstA + (uint32_t)(row * 128 + lcS * 16),
                       Abase + (size_t)row * M_ + k0 + lc * 8);
        }
        #pragma unroll
        for (int i = 0; i < 4; i++) {
            int row = lrow + i * 32;
            cp_async16(dstB + (uint32_t)(row * 128 + lcS * 16),
                       Bbase + (size_t)row * M_ + k0 + lc * 8);
        }
        CP_ASYNC_COMMIT();
    };

    // ---- ldmatrix lane-constant addressing ----
    int rwl = lane & 7;
    int rowA = warp_m * 32 + rwl + ((lane >> 3) & 1) * 8;
    int khA  = (lane >> 4) & 1;
    uint32_t baseA = (uint32_t)(rowA * 128);
    int rowB = warp_n * 64 + rwl + ((lane >> 4) & 1) * 8;
    int khB  = (lane >> 3) & 1;
    uint32_t baseB = (uint32_t)(rowB * 128);
    uint32_t offA[4], offB[4];
    #pragma unroll
    for (int ks = 0; ks < 4; ks++) {
        offA[ks] = (uint32_t)(((2 * ks + khA) ^ rwl) * 16);
        offB[ks] = (uint32_t)(((2 * ks + khB) ^ rwl) * 16);
    }

    float acc[2][8][4];
    #pragma unroll
    for (int mt = 0; mt < 2; mt++)
        #pragma unroll
        for (int nt = 0; nt < 8; nt++)
            #pragma unroll
            for (int i = 0; i < 4; i++)
                acc[mt][nt][i] = 0.0f;

    load_stage(0, 0);
    load_stage(1, 1);

    uint32_t bfr[2][16];    // double-buffered B fragments (ks level)

    for (int kt = 0; kt < 16; kt++) {
        if (kt == 15) { CP_ASYNC_WAIT(0); } else { CP_ASYNC_WAIT(1); }
        __syncthreads();

        if (kt + 2 < 16) load_stage(kt + 2, (kt + 2) % 3);

        uint32_t stq   = smem_base + (uint32_t)(kt % 3) * STAGE_BYTES;
        uint32_t aAddr = stq + baseA;
        uint32_t bAddr = stq + AH_BYTES + baseB;

        // preload B fragments for ks=0
        #pragma unroll
        for (int ntp = 0; ntp < 4; ntp++)
            ldsm4(bfr[0][ntp * 4 + 0], bfr[0][ntp * 4 + 1],
                  bfr[0][ntp * 4 + 2], bfr[0][ntp * 4 + 3],
                  bAddr + (uint32_t)(ntp * 16 * 128) + offB[0]);

        #pragma unroll
        for (int ks = 0; ks < 4; ks++) {       // 4 x k16 = K 64
            int cur = ks & 1;
            if (ks < 3) {
                int nxt = cur ^ 1;
                #pragma unroll
                for (int ntp = 0; ntp < 4; ntp++)
                    ldsm4(bfr[nxt][ntp * 4 + 0], bfr[nxt][ntp * 4 + 1],
                          bfr[nxt][ntp * 4 + 2], bfr[nxt][ntp * 4 + 3],
                          bAddr + (uint32_t)(ntp * 16 * 128) + offB[ks + 1]);
            }
            #pragma unroll
            for (int mt = 0; mt < 2; mt++) {
                uint32_t a0, a1, a2, a3;
                ldsm4(a0, a1, a2, a3,
                      aAddr + (uint32_t)(mt * 16 * 128) + offA[ks]);
                #pragma unroll
                for (int nt = 0; nt < 8; nt++) {
                    int bi = (nt >> 1) * 4 + (nt & 1) * 2;
                    mma_f16(acc[mt][nt], a0, a1, a2, a3,
                            bfr[cur][bi], bfr[cur][bi + 1]);
                }
            }
        }
    }

    // ---- epilogue: spart[dblk][s] = sum_d Wv[d]*tanh(C + decf[d]) ----
    __syncthreads();
    float* s_df = smem;           // [128]
    float* s_wv = smem + 128;     // [128]
    if (tid < 128) {
        int gi = b * D_ + d_base + tid;
        float df = g_decf8[0][gi];
        #pragma unroll
        for (int c = 1; c < 8; c++) df += g_decf8[c][gi];
        s_df[tid] = df;
    } else {
        s_wv[tid - 128] = W_v[d_base + tid - 128];
    }
    __syncthreads();

    float part[4] = {0.f, 0.f, 0.f, 0.f};
    #pragma unroll
    for (int mt = 0; mt < 2; mt++) {
        #pragma unroll
        for (int nt = 0; nt < 8; nt++) {
            int col0 = warp_n * 64 + nt * 8 + 2 * q;
            float wv0 = s_wv[col0], wv1 = s_wv[col0 + 1];
            float df0 = s_df[col0], df1 = s_df[col0 + 1];
            part[2 * mt]     += wv0 * tanh_fast(acc[mt][nt][0] + df0)
                              + wv1 * tanh_fast(acc[mt][nt][1] + df1);
            part[2 * mt + 1] += wv0 * tanh_fast(acc[mt][nt][2] + df0)
                              + wv1 * tanh_fast(acc[mt][nt][3] + df1);
        }
    }
    #pragma unroll
    for (int i = 0; i < 4; i++) {
        part[i] += __shfl_xor_sync(0xFFFFFFFFu, part[i], 1);
        part[i] += __shfl_xor_sync(0xFFFFFFFFu, part[i], 2);
    }
    // warp_n=0 and warp_n=1 cover different d-halves of the same rows;
    // keep them in different partial buffers: pidx = blockIdx.x is per
    // 128-wide d-tile -> two warp_n halves must be summed. Use shared
    // reduction across the two warp_n groups via the 8 partial slots:
    // slot = blockIdx.x covers warp_n 0; add warp_n's half separately.
    if (q == 0) {
        int grp = lane >> 2;
        int rbase = b * S_ + s_base + warp_m * 32 + grp;
        float* dst = g_spart[blockIdx.x];
        if (warp_n == 0) {
            dst[rbase]      = part[0];
            dst[rbase + 8]  = part[1];
            dst[rbase + 16] = part[2];
            dst[rbase + 24] = part[3];
        }
    }
    __syncthreads();              // warp_n=0 stores visible? (global: use atomics-free 2-step)
    if (q == 0 && warp_n == 1) {
        int grp = lane >> 2;
        int rbase = b * S_ + s_base + warp_m * 32 + grp;
        float* dst = g_spart[blockIdx.x];
        dst[rbase]      += part[0];
        dst[rbase + 8]  += part[1];
        dst[rbase + 16] += part[2];
        dst[rbase + 24] += part[3];
    }
}

// ---------------------------------------------------------------------------
// Fused masked softmax + context (context reads fp16 memory copy).
// grid (8 s-chunks of 256, 64 b), block 256.  Scores = sum of 8 partials.
// ---------------------------------------------------------------------------
#define CCHUNK 256

__global__ __launch_bounds__(256) void softmax_context_kernel(
    const int* __restrict__ src_mask,
    float* __restrict__ attn_out,
    float* __restrict__ ctx_out)
{
    __shared__ float red[8];
    __shared__ float sa[CCHUNK];
    int tid = threadIdx.x;
    int lane = tid & 31, wid = tid >> 5;
    int b  = blockIdx.y;
    int s0 = blockIdx.x * CCHUNK;

    // ---- softmax stats over the whole row (identical in all 8 CTAs of b) ----
    float v[8];
    float mx = -3.4e38f;
    #pragma unroll
    for (int j = 0; j < 8; j++) {
        int idx = b * S_ + tid + j * 256;
        float s = g_spart[0][idx];
        #pragma unroll
        for (int c = 1; c < 8; c++) s += g_spart[c][idx];
        if (src_mask[idx] == 0) s = -3.4e38f;
        v[j] = s;
        mx = fmaxf(mx, s);
    }
    #pragma unroll
    for (int off = 16; off > 0; off >>= 1)
        mx = fmaxf(mx, __shfl_xor_sync(0xFFFFFFFFu, mx, off));
    if (lane == 0) red[wid] = mx;
    __syncthreads();
    if (tid == 0) {
        float m2 = red[0];
        #pragma unroll
        for (int w = 1; w < 8; w++) m2 = fmaxf(m2, red[w]);
        red[0] = m2;
    }
    __syncthreads();
    mx = red[0];
    __syncthreads();

    float sum = 0.0f;
    #pragma unroll
    for (int j = 0; j < 8; j++)
        sum += __expf(v[j] - mx);
    #pragma unroll
    for (int off = 16; off > 0; off >>= 1)
        sum += __shfl_xor_sync(0xFFFFFFFFu, sum, off);
    if (lane == 0) red[wid] = sum;
    __syncthreads();
    if (tid == 0) {
        float s2 = 0.0f;
        #pragma unroll
        for (int w = 0; w < 8; w++) s2 += red[w];
        red[0] = s2;
    }
    __syncthreads();
    float inv = 1.0f / red[0];

    // ---- attn for this CTA's chunk ----
    float a = __expf(v[blockIdx.x] - mx) * inv;
    attn_out[b * S_ + s0 + tid] = a;
    sa[tid] = a;
    __syncthreads();

    // ---- context partial from fp16 memory: 8 m per thread, 2-way s split ----
    int mgrp = (tid & 127) * 8;               // 8 consecutive m
    int sp   = tid >> 7;                      // s parity 0/1
    const uint4* base = reinterpret_cast<const uint4*>(
        g_memh + ((size_t)b * S_ + s0) * M_ + mgrp);
    float acc[8];
    #pragma unroll
    for (int i = 0; i < 8; i++) acc[i] = 0.0f;

    for (int s = sp; s < CCHUNK; s += 2) {
        float w = sa[s];
        uint4 pk = base[(size_t)s * (M_ / 8)];
        __half2 h0 = *reinterpret_cast<__half2*>(&pk.x);
        __half2 h1 = *reinterpret_cast<__half2*>(&pk.y);
        __half2 h2 = *reinterpret_cast<__half2*>(&pk.z);
        __half2 h3 = *reinterpret_cast<__half2*>(&pk.w);
        float2 f0 = __half22float2(h0);
        float2 f1 = __half22float2(h1);
        float2 f2 = __half22float2(h2);
        float2 f3 = __half22float2(h3);
        acc[0] += w * f0.x; acc[1] += w * f0.y;
        acc[2] += w * f1.x; acc[3] += w * f1.y;
        acc[4] += w * f2.x; acc[5] += w * f2.y;
        acc[6] += w * f3.x; acc[7] += w * f3.y;
    }
    float* dst = ctx_out + b * M_ + mgrp;
    #pragma unroll
    for (int i = 0; i < 8; i++)
        atomicAdd(dst + i, acc[i]);
}

// ---------------------------------------------------------------------------
// Launch
// ---------------------------------------------------------------------------
extern "C" void kernel_launch(void* const* d_in, const int* in_sizes, int n_in,
                              void* d_out, int out_size)
{
    const float* decoder_state = (const float*)d_in[0];
    const float* memory_bank   = (const float*)d_in[1];
    const int*   src_mask      = (const int*)  d_in[2];
    const float* W_v           = (const float*)d_in[3];
    const float* W_dec         = (const float*)d_in[4];
    const float* W_mem         = (const float*)d_in[5];

    float* out  = (float*)d_out;
    float* ctx  = out;                 // [64, 1024]
    float* attn = out + B_ * M_;       // [64, 2048]

    cudaFuncSetAttribute(scores_mma_kernel,
                         cudaFuncAttributeMaxDynamicSharedMemorySize, SM_BYTES);

    prep_kernel<<<PREP_NB, 256>>>(W_mem, decoder_state, W_dec, memory_bank, ctx);
    scores_mma_kernel<<<dim3(D_ / 128, S_ / 128, B_), 256, SM_BYTES>>>(W_v);
    softmax_context_kernel<<<dim3(S_ / CCHUNK, B_), 256>>>(src_mask, attn, ctx);
}